// round 10
// baseline (speedup 1.0000x reference)
#include <cuda_runtime.h>
#include <math.h>

// LWM cross attention, fully fused: per-window 1x1-conv GEMMs (q, kv) +
// linear-attention epilogue. One CTA per 16x16 window.
// R2: 4x4 register-tiled GEMMs with transposed weight stage (2 B/FMA LDS),
//     Q phase processes 2 heads per iteration so all 512 threads work.

namespace {
constexpr int Bn    = 8;
constexpr int C     = 128;
constexpr int Hdim  = 256;
constexpr int Wdim  = 256;
constexpr int NHm   = 8;
constexpr int D     = 16;     // head dim
constexpr int WSz   = 16;     // window size
constexpr int NPix  = 256;    // pixels per window
constexpr int NWin  = Bn * 16 * 16;  // 2048
constexpr int THREADS = 512;
constexpr float EPSf = 1e-6f;

constexpr int KVH_STRIDE = 260;  // 32x256 head buffer rows (16B-aligned)
constexpr int WT_STRIDE  = 36;   // transposed weight stage: wt[c][j], 16B-aligned rows

// shared memory layout (in floats)
constexpr int OFF_XS    = 0;                         // x tile [128][256]
constexpr int OFF_KVH   = OFF_XS + C * NPix;         // head buffer [32][260]
constexpr int OFF_WSA   = OFF_KVH + 32 * KVH_STRIDE; // weight stage [128][36] (transposed)
constexpr int OFF_INV   = OFF_WSA + C * WT_STRIDE;   // per-pixel 1/||k|| [256]
constexpr int OFF_KVACC = OFF_INV + NPix;            // kv_acc [8][16][16]
constexpr int OFF_KSUM  = OFF_KVACC + NHm * D * D;   // ksum [8][16]
constexpr int OFF_VSUM  = OFF_KSUM + NHm * D;        // vsum [8][16]
constexpr int SMEM_FLOATS = OFF_VSUM + NHm * D;      // 48256
constexpr int SMEM_BYTES  = SMEM_FLOATS * 4;         // 193024
}

__global__ void __launch_bounds__(THREADS, 1)
lwm_kernel(const float* __restrict__ x1, const float* __restrict__ x2,
           const float* __restrict__ Wq, const float* __restrict__ Wkv,
           float* __restrict__ out)
{
    extern __shared__ float sm[];
    float* xs    = sm + OFF_XS;
    float* kvh   = sm + OFF_KVH;
    float* wsa   = sm + OFF_WSA;
    float* invb  = sm + OFF_INV;
    float* kvacc = sm + OFF_KVACC;
    float* ksum  = sm + OFF_KSUM;
    float* vsum  = sm + OFF_VSUM;

    const int win = blockIdx.x;
    const int wx  = win & 15;
    const int wy  = (win >> 4) & 15;
    const int b   = win >> 8;
    const int t   = threadIdx.x;
    const int lane = t & 31;
    const int warp = t >> 5;

    const size_t base = (size_t)b * (C * Hdim * Wdim)
                      + (size_t)(wy * WSz) * Wdim + (size_t)(wx * WSz);
    const int CH_STRIDE = Hdim * Wdim;  // 65536

    // ---- tile loader: x[c][n] for this window, float4 vectorized ----
    auto load_tile = [&](const float* __restrict__ src) {
        for (int idx = t; idx < (C * NPix) / 4; idx += THREADS) {
            int c  = idx >> 6;
            int n4 = (idx & 63) << 2;
            int r  = n4 >> 4, s = n4 & 15;
            float4 v = *reinterpret_cast<const float4*>(
                src + base + (size_t)c * CH_STRIDE + r * Wdim + s);
            *reinterpret_cast<float4*>(xs + c * NPix + n4) = v;
        }
    };

    // ---- 32x256 GEMM from transposed weight stage into kvh ----
    // thread tile: 4 j x 4 n.  lane -> (jt = lane&7, nt = lane>>3), warp -> 16-px n-block
    auto gemm32 = [&]() {
        const int jt = lane & 7;
        const int nt = lane >> 3;
        const int n0 = warp * 16 + nt * 4;
        float a0x=0.f,a0y=0.f,a0z=0.f,a0w=0.f;
        float a1x=0.f,a1y=0.f,a1z=0.f,a1w=0.f;
        float a2x=0.f,a2y=0.f,a2z=0.f,a2w=0.f;
        float a3x=0.f,a3y=0.f,a3z=0.f,a3w=0.f;
        const float* wp = wsa + jt * 4;
        const float* xp = xs + n0;
#pragma unroll 4
        for (int c = 0; c < C; ++c) {
            float4 w4 = *reinterpret_cast<const float4*>(wp + c * WT_STRIDE);
            float4 x4 = *reinterpret_cast<const float4*>(xp + c * NPix);
            a0x += w4.x * x4.x; a0y += w4.x * x4.y; a0z += w4.x * x4.z; a0w += w4.x * x4.w;
            a1x += w4.y * x4.x; a1y += w4.y * x4.y; a1z += w4.y * x4.z; a1w += w4.y * x4.w;
            a2x += w4.z * x4.x; a2y += w4.z * x4.y; a2z += w4.z * x4.z; a2w += w4.z * x4.w;
            a3x += w4.w * x4.x; a3y += w4.w * x4.y; a3z += w4.w * x4.z; a3w += w4.w * x4.w;
        }
        float* kd = kvh + (jt * 4) * KVH_STRIDE + n0;
        *reinterpret_cast<float4*>(kd)                  = make_float4(a0x,a0y,a0z,a0w);
        *reinterpret_cast<float4*>(kd + KVH_STRIDE)     = make_float4(a1x,a1y,a1z,a1w);
        *reinterpret_cast<float4*>(kd + 2*KVH_STRIDE)   = make_float4(a2x,a2y,a2z,a2w);
        *reinterpret_cast<float4*>(kd + 3*KVH_STRIDE)   = make_float4(a3x,a3y,a3z,a3w);
    };

    // =============== Phase A: K/V per head -> summaries ===============
    load_tile(x2);

    for (int h = 0; h < NHm; ++h) {
        // stage transposed weights: 16 K rows + 16 V rows of this head
        for (int idx = t; idx < 32 * C; idx += THREADS) {
            int j = idx >> 7, c = idx & 127;
            int row = (j < 16) ? (h * 16 + j) : (C + h * 16 + (j - 16));
            wsa[c * WT_STRIDE + j] = Wkv[row * C + c];
        }
        __syncthreads();

        gemm32();
        __syncthreads();

        // per-pixel inverse norm of k column
        if (t < NPix) {
            float ss = 0.f;
#pragma unroll
            for (int dd = 0; dd < 16; ++dd) {
                float kk = kvh[dd * KVH_STRIDE + t];
                ss += kk * kk;
            }
            invb[t] = rsqrtf(ss);
        }
        __syncthreads();

        // kv_acc[m][c] = sum_n k_norm[m,n] * v[c,n]; ksum, vsum folded in
        if (t < 256) {
            const int m  = t >> 4;
            const int cc = t & 15;
            const float4* kp = reinterpret_cast<const float4*>(kvh + m * KVH_STRIDE);
            const float4* vp = reinterpret_cast<const float4*>(kvh + (16 + cc) * KVH_STRIDE);
            const float4* ip = reinterpret_cast<const float4*>(invb);
            float a = 0.f, ks = 0.f, vs = 0.f;
#pragma unroll 4
            for (int qn = 0; qn < 64; ++qn) {
                float4 kk = kp[qn], vv = vp[qn], iv = ip[qn];
                float k0 = kk.x * iv.x, k1 = kk.y * iv.y;
                float k2 = kk.z * iv.z, k3 = kk.w * iv.w;
                a  += k0 * vv.x + k1 * vv.y + k2 * vv.z + k3 * vv.w;
                ks += (k0 + k1) + (k2 + k3);
                vs += (vv.x + vv.y) + (vv.z + vv.w);
            }
            kvacc[(h * 16 + m) * 16 + cc] = a;
            if (cc == 0) ksum[h * 16 + m] = ks;
            if (m == 0)  vsum[h * 16 + cc] = vs;
        }
        // next iteration's post-stage sync orders kvacc reads vs next GEMM stores
    }

    // =============== Phase B: Q, two heads per iteration ===============
    load_tile(x1);

    for (int hp = 0; hp < NHm / 2; ++hp) {
        // stage transposed Wq rows [hp*32, hp*32+32) = heads 2hp and 2hp+1
        for (int idx = t; idx < 32 * C; idx += THREADS) {
            int j = idx >> 7, c = idx & 127;
            wsa[c * WT_STRIDE + j] = Wq[(hp * 32 + j) * C + c];
        }
        __syncthreads();

        gemm32();   // q rows: j<16 -> head 2hp, j>=16 -> head 2hp+1
        __syncthreads();

        // epilogue: one (pixel, head) per thread, full 16 output channels
        {
            const int n    = t >> 1;
            const int hh   = t & 1;
            const int head = hp * 2 + hh;

            float qv[16];
            float ss = 0.f;
#pragma unroll
            for (int dd = 0; dd < 16; ++dd) {
                float q = kvh[(hh * 16 + dd) * KVH_STRIDE + n];
                qv[dd] = q;
                ss += q * q;
            }
            float inv = rsqrtf(ss);
            float dot = 0.f;
#pragma unroll
            for (int dd = 0; dd < 16; ++dd) {
                qv[dd] *= inv;
                dot += qv[dd] * (ksum[head * 16 + dd] + EPSf);
            }
            float tail = 1.0f / (256.0f + dot);

            float o[16];
            {
                const float4* vs4 = reinterpret_cast<const float4*>(vsum + head * 16);
#pragma unroll
                for (int q4 = 0; q4 < 4; ++q4) {
                    float4 v = vs4[q4];
                    o[q4*4+0] = v.x; o[q4*4+1] = v.y; o[q4*4+2] = v.z; o[q4*4+3] = v.w;
                }
            }
#pragma unroll
            for (int m2 = 0; m2 < 16; ++m2) {
                float q = qv[m2];
                const float4* kr = reinterpret_cast<const float4*>(kvacc + (head * 16 + m2) * 16);
#pragma unroll
                for (int q4 = 0; q4 < 4; ++q4) {
                    float4 v = kr[q4];
                    o[q4*4+0] += q * v.x; o[q4*4+1] += q * v.y;
                    o[q4*4+2] += q * v.z; o[q4*4+3] += q * v.w;
                }
            }

            const int r = n >> 4, s2 = n & 15;
            const size_t g0 = base + (size_t)(head * 16) * CH_STRIDE
                            + (size_t)r * Wdim + s2;
#pragma unroll
            for (int c2 = 0; c2 < 16; ++c2)
                out[g0 + (size_t)c2 * CH_STRIDE] = o[c2] * tail;
        }
        // next iteration's post-stage sync orders epilogue kvh reads vs next GEMM stores
    }
}

extern "C" void kernel_launch(void* const* d_in, const int* in_sizes, int n_in,
                              void* d_out, int out_size) {
    const float* x1  = (const float*)d_in[0];
    const float* x2  = (const float*)d_in[1];
    const float* Wq  = (const float*)d_in[2];
    const float* Wkv = (const float*)d_in[3];
    float* out = (float*)d_out;

    cudaFuncSetAttribute(lwm_kernel, cudaFuncAttributeMaxDynamicSharedMemorySize, SMEM_BYTES);
    lwm_kernel<<<NWin, THREADS, SMEM_BYTES>>>(x1, x2, Wq, Wkv, out);
}

// round 16
// speedup vs baseline: 1.6077x; 1.6077x over previous
#include <cuda_runtime.h>
#include <cuda_bf16.h>
#include <cstdint>
#include <math.h>

// LWM cross attention, fused, mma.sync (bf16 hi/lo 3-pass) edition.
// One CTA per 16x16 window; K/V/Q GEMMs on the tensor pipe via
// mma.sync.m16n8k16; kv_acc contracted in registers from K/V fragments.

namespace {
constexpr int C       = 128;
constexpr int Wdim    = 256;
constexpr int NWin    = 2048;
constexpr int THREADS = 512;
constexpr float EPSf  = 1e-6f;
constexpr int CH      = 65536;    // H*W plane stride

constexpr int RSP = 68;           // x-plane row stride in 32-bit words (64 pairs + pad)
constexpr int XHI = 0;            // x hi plane [256n][RSP] uint32 (bf16x2)  69632 B
constexpr int XLO = 69632;        // x lo plane                              69632 B
constexpr int OFF_KVACC = 139264; // kv_acc [8][16][16] fp32 (8192 B)
constexpr int OFF_KSUM  = 147456; // [128] fp32
constexpr int OFF_VSUM  = 147968; // [128] fp32
constexpr int SMEM_BYTES = 148480;
constexpr int QD_STRIDE = 132;    // Q dump fp32 [256n][132] (reuses x planes; 135168 B)
}

// ---- mma.sync m16n8k16 row.col f32 <- bf16 x bf16 + f32 (D == C accumulate) ----
__device__ __forceinline__ void mma16816(float* d, const uint32_t* a, uint32_t b0, uint32_t b1) {
    asm volatile(
        "mma.sync.aligned.m16n8k16.row.col.f32.bf16.bf16.f32 "
        "{%0,%1,%2,%3}, {%4,%5,%6,%7}, {%8,%9}, {%0,%1,%2,%3};"
        : "+f"(d[0]), "+f"(d[1]), "+f"(d[2]), "+f"(d[3])
        : "r"(a[0]), "r"(a[1]), "r"(a[2]), "r"(a[3]), "r"(b0), "r"(b1));
}

// pack (x,y) into bf16x2 hi estimate + bf16x2 residual
__device__ __forceinline__ void pack_hilo(float x, float y, uint32_t& h, uint32_t& l) {
    __nv_bfloat162 hb = __floats2bfloat162_rn(x, y);
    float xr = x - __bfloat162float(hb.x);
    float yr = y - __bfloat162float(hb.y);
    __nv_bfloat162 lb = __floats2bfloat162_rn(xr, yr);
    h = *reinterpret_cast<uint32_t*>(&hb);
    l = *reinterpret_cast<uint32_t*>(&lb);
}

// A-fragment source: 4 fp32 pairs from a global weight row pair.
// wrow = W + (j0 + lane/4)*C.  Order: (r,k),(r+8,k),(r,k+8),(r+8,k+8).
__device__ __forceinline__ void loadA(const float* __restrict__ wrow, int kc, int tq, float2* p) {
    const float* bp = wrow + kc * 16 + 2 * tq;
    p[0] = *reinterpret_cast<const float2*>(bp);
    p[1] = *reinterpret_cast<const float2*>(bp + 8 * C);
    p[2] = *reinterpret_cast<const float2*>(bp + 8);
    p[3] = *reinterpret_cast<const float2*>(bp + 8 * C + 8);
}
__device__ __forceinline__ void cvtA(const float2* p, uint32_t* h, uint32_t* l) {
#pragma unroll
    for (int i = 0; i < 4; ++i) pack_hilo(p[i].x, p[i].y, h[i], l[i]);
}

__global__ void __launch_bounds__(THREADS, 1)
lwm_kernel(const float* __restrict__ x1, const float* __restrict__ x2,
           const float* __restrict__ Wq, const float* __restrict__ Wkv,
           float* __restrict__ out)
{
    extern __shared__ char smc[];
    uint32_t* xh = reinterpret_cast<uint32_t*>(smc + XHI);
    uint32_t* xl = reinterpret_cast<uint32_t*>(smc + XLO);
    float* kvacc = reinterpret_cast<float*>(smc + OFF_KVACC);
    float* ksum  = reinterpret_cast<float*>(smc + OFF_KSUM);
    float* vsum  = reinterpret_cast<float*>(smc + OFF_VSUM);
    float* qd    = reinterpret_cast<float*>(smc);   // valid once x planes are dead

    const int t    = threadIdx.x;
    const int lane = t & 31;
    const int warp = t >> 5;
    const int r    = lane >> 2;   // 0..7  (A row group / B col)
    const int tq   = lane & 3;    // 0..3  (k / D-col group)

    const int win = blockIdx.x;
    const int wx  = win & 15;
    const int wy  = (win >> 4) & 15;
    const int b   = win >> 8;
    const size_t base = (size_t)b * (C * CH) + (size_t)(wy * 16) * Wdim + (size_t)(wx * 16);

    // ---- x stage: fp32 [c][pix] -> bf16 hi/lo transposed [n][c-pair] ----
    auto stage_x = [&](const float* __restrict__ src) {
        const int cp = t & 63;           // channel pair
        const int q  = t >> 6;           // 0..7 -> pixels 32q..32q+31
        const float* p0 = src + base + (size_t)(2 * cp) * CH + (size_t)(q * 2) * Wdim;
        const float* p1 = p0 + CH;
#pragma unroll
        for (int half = 0; half < 2; ++half) {
#pragma unroll
            for (int j4 = 0; j4 < 4; ++j4) {
                float4 u0 = *reinterpret_cast<const float4*>(p0 + half * Wdim + j4 * 4);
                float4 u1 = *reinterpret_cast<const float4*>(p1 + half * Wdim + j4 * 4);
                int nb = q * 32 + half * 16 + j4 * 4;
                float a0[4] = {u0.x, u0.y, u0.z, u0.w};
                float a1[4] = {u1.x, u1.y, u1.z, u1.w};
#pragma unroll
                for (int e = 0; e < 4; ++e) {
                    uint32_t h, l;
                    pack_hilo(a0[e], a1[e], h, l);
                    xh[(nb + e) * RSP + cp] = h;
                    xl[(nb + e) * RSP + cp] = l;
                }
            }
        }
    };

    // =============== Phase A: stage x2, zero summaries ===============
    stage_x(x2);
    kvacc[t] = 0.f; kvacc[t + 512] = 0.f; kvacc[t + 1024] = 0.f; kvacc[t + 1536] = 0.f;
    if (t < 128) { ksum[t] = 0.f; vsum[t] = 0.f; }
    __syncthreads();

    // =============== K/V GEMMs + fused summaries, 2 units per warp ===============
#pragma unroll 1
    for (int u = 0; u < 2; ++u) {
        const int unit = warp * 2 + u;
        const int head = unit >> 2;
        const int n0   = (unit & 3) * 64;
        const float* wkr = Wkv + (size_t)(head * 16 + r) * C;
        const float* wvr = Wkv + (size_t)(128 + head * 16 + r) * C;

        float kacc[8][4], vacc[8][4];
#pragma unroll
        for (int ns = 0; ns < 8; ++ns)
#pragma unroll
            for (int i = 0; i < 4; ++i) { kacc[ns][i] = 0.f; vacc[ns][i] = 0.f; }

#pragma unroll 1
        for (int kc = 0; kc < 8; ++kc) {
            float2 pk[4], pv[4];
            loadA(wkr, kc, tq, pk);
            loadA(wvr, kc, tq, pv);
            uint32_t kh[4], klr[4], vh[4], vlr[4];
            cvtA(pk, kh, klr);
            cvtA(pv, vh, vlr);
#pragma unroll
            for (int ns = 0; ns < 8; ++ns) {
                int bi = (n0 + ns * 8 + r) * RSP + kc * 8 + tq;
                uint32_t b0h = xh[bi], b1h = xh[bi + 4];
                uint32_t b0l = xl[bi], b1l = xl[bi + 4];
                mma16816(kacc[ns], kh, b0h, b1h);
                mma16816(kacc[ns], kh, b0l, b1l);
                mma16816(kacc[ns], klr, b0h, b1h);
                mma16816(vacc[ns], vh, b0h, b1h);
                mma16816(vacc[ns], vh, b0l, b1l);
                mma16816(vacc[ns], vlr, b0h, b1h);
            }
        }

        // normalize K columns over the head's 16 rows (reduce across row-groups)
#pragma unroll
        for (int ns = 0; ns < 8; ++ns) {
            float ss0 = kacc[ns][0] * kacc[ns][0] + kacc[ns][2] * kacc[ns][2];
            float ss1 = kacc[ns][1] * kacc[ns][1] + kacc[ns][3] * kacc[ns][3];
#pragma unroll
            for (int off = 4; off < 32; off <<= 1) {
                ss0 += __shfl_xor_sync(0xffffffffu, ss0, off);
                ss1 += __shfl_xor_sync(0xffffffffu, ss1, off);
            }
            float r0 = rsqrtf(ss0), r1 = rsqrtf(ss1);
            kacc[ns][0] *= r0; kacc[ns][2] *= r0;
            kacc[ns][1] *= r1; kacc[ns][3] *= r1;
        }

        // ksum / vsum row partials: reduce over D-col lanes (tq), atomic into smem
        {
            float slo = 0.f, shi = 0.f, wlo = 0.f, whi = 0.f;
#pragma unroll
            for (int ns = 0; ns < 8; ++ns) {
                slo += kacc[ns][0] + kacc[ns][1];
                shi += kacc[ns][2] + kacc[ns][3];
                wlo += vacc[ns][0] + vacc[ns][1];
                whi += vacc[ns][2] + vacc[ns][3];
            }
#pragma unroll
            for (int off = 1; off < 4; off <<= 1) {
                slo += __shfl_xor_sync(0xffffffffu, slo, off);
                shi += __shfl_xor_sync(0xffffffffu, shi, off);
                wlo += __shfl_xor_sync(0xffffffffu, wlo, off);
                whi += __shfl_xor_sync(0xffffffffu, whi, off);
            }
            if (tq == 0) {
                atomicAdd(ksum + head * 16 + r,     slo);
                atomicAdd(ksum + head * 16 + r + 8, shi);
                atomicAdd(vsum + head * 16 + r,     wlo);
                atomicAdd(vsum + head * 16 + r + 8, whi);
            }
        }

        // kv_acc[m][c] += sum_n khat[m][n] * V[c][n]  — in-register repack mma
        {
            float kvA[4] = {0.f, 0.f, 0.f, 0.f};   // c = 0..7
            float kvB[4] = {0.f, 0.f, 0.f, 0.f};   // c = 8..15
#pragma unroll
            for (int ch = 0; ch < 4; ++ch) {
                uint32_t ah[4], al[4];
                pack_hilo(kacc[2*ch][0],   kacc[2*ch][1],   ah[0], al[0]);
                pack_hilo(kacc[2*ch][2],   kacc[2*ch][3],   ah[1], al[1]);
                pack_hilo(kacc[2*ch+1][0], kacc[2*ch+1][1], ah[2], al[2]);
                pack_hilo(kacc[2*ch+1][2], kacc[2*ch+1][3], ah[3], al[3]);
                uint32_t b0h, b0l, b1h, b1l, c0h, c0l, c1h, c1l;
                pack_hilo(vacc[2*ch][0],   vacc[2*ch][1],   b0h, b0l);
                pack_hilo(vacc[2*ch+1][0], vacc[2*ch+1][1], b1h, b1l);
                pack_hilo(vacc[2*ch][2],   vacc[2*ch][3],   c0h, c0l);
                pack_hilo(vacc[2*ch+1][2], vacc[2*ch+1][3], c1h, c1l);
                mma16816(kvA, ah, b0h, b1h);
                mma16816(kvA, ah, b0l, b1l);
                mma16816(kvA, al, b0h, b1h);
                mma16816(kvB, ah, c0h, c1h);
                mma16816(kvB, ah, c0l, c1l);
                mma16816(kvB, al, c0h, c1h);
            }
            float* kb = kvacc + (head * 16 + r) * 16;
            atomicAdd(kb + 2 * tq,                kvA[0]);
            atomicAdd(kb + 2 * tq + 1,            kvA[1]);
            atomicAdd(kb + 8 * 16 + 2 * tq,       kvA[2]);
            atomicAdd(kb + 8 * 16 + 2 * tq + 1,   kvA[3]);
            atomicAdd(kb + 8 + 2 * tq,            kvB[0]);
            atomicAdd(kb + 8 + 2 * tq + 1,        kvB[1]);
            atomicAdd(kb + 8 * 16 + 8 + 2 * tq,   kvB[2]);
            atomicAdd(kb + 8 * 16 + 8 + 2 * tq + 1, kvB[3]);
        }
    }

    __syncthreads();             // all x2 reads + summary atomics done

    // =============== Phase B: Q GEMM (2 units/warp), keep fragments ===============
    stage_x(x1);
    __syncthreads();

    float qacc[2][8][4];
#pragma unroll 1
    for (int u = 0; u < 2; ++u) {
        const int unit = warp * 2 + u;
        const int head = unit >> 2;
        const int n0   = (unit & 3) * 64;
        const float* wqr = Wq + (size_t)(head * 16 + r) * C;

#pragma unroll
        for (int ns = 0; ns < 8; ++ns)
#pragma unroll
            for (int i = 0; i < 4; ++i) qacc[u][ns][i] = 0.f;

#pragma unroll 1
        for (int kc = 0; kc < 8; ++kc) {
            float2 pq[4];
            loadA(wqr, kc, tq, pq);
            uint32_t qh[4], qlr[4];
            cvtA(pq, qh, qlr);
#pragma unroll
            for (int ns = 0; ns < 8; ++ns) {
                int bi = (n0 + ns * 8 + r) * RSP + kc * 8 + tq;
                uint32_t b0h = xh[bi], b1h = xh[bi + 4];
                uint32_t b0l = xl[bi], b1l = xl[bi + 4];
                mma16816(qacc[u][ns], qh, b0h, b1h);
                mma16816(qacc[u][ns], qh, b0l, b1l);
                mma16816(qacc[u][ns], qlr, b0h, b1h);
            }
        }

        // normalize Q columns over the head's 16 rows
#pragma unroll
        for (int ns = 0; ns < 8; ++ns) {
            float ss0 = qacc[u][ns][0] * qacc[u][ns][0] + qacc[u][ns][2] * qacc[u][ns][2];
            float ss1 = qacc[u][ns][1] * qacc[u][ns][1] + qacc[u][ns][3] * qacc[u][ns][3];
#pragma unroll
            for (int off = 4; off < 32; off <<= 1) {
                ss0 += __shfl_xor_sync(0xffffffffu, ss0, off);
                ss1 += __shfl_xor_sync(0xffffffffu, ss1, off);
            }
            float r0 = rsqrtf(ss0), r1 = rsqrtf(ss1);
            qacc[u][ns][0] *= r0; qacc[u][ns][2] *= r0;
            qacc[u][ns][1] *= r1; qacc[u][ns][3] *= r1;
        }
    }

    __syncthreads();             // all x1 reads done; planes reusable as qd

    // dump qhat fp32 [n][m] (conflict-free: bank = 8*tq + r)
#pragma unroll
    for (int u = 0; u < 2; ++u) {
        const int unit = warp * 2 + u;
        const int head = unit >> 2;
        const int n0   = (unit & 3) * 64;
        const int m0   = head * 16 + r;
#pragma unroll
        for (int ns = 0; ns < 8; ++ns) {
            int nb = n0 + ns * 8 + 2 * tq;
            qd[nb * QD_STRIDE + m0]           = qacc[u][ns][0];
            qd[(nb + 1) * QD_STRIDE + m0]     = qacc[u][ns][1];
            qd[nb * QD_STRIDE + m0 + 8]       = qacc[u][ns][2];
            qd[(nb + 1) * QD_STRIDE + m0 + 8] = qacc[u][ns][3];
        }
    }
    __syncthreads();

    // =============== Epilogue: out[c][n] = (qhat·kv_acc + vsum) * tailor ===============
#pragma unroll
    for (int it = 0; it < 4; ++it) {
        int id   = t + it * 512;
        int head = id >> 8, n = id & 255;

        const float* qrow = qd + n * QD_STRIDE + head * 16;
        float qv[16];
#pragma unroll
        for (int q4 = 0; q4 < 4; ++q4) {
            float4 v = reinterpret_cast<const float4*>(qrow)[q4];
            qv[q4*4+0] = v.x; qv[q4*4+1] = v.y; qv[q4*4+2] = v.z; qv[q4*4+3] = v.w;
        }
        float dot = 0.f;
#pragma unroll
        for (int dd = 0; dd < 16; ++dd)
            dot += qv[dd] * (ksum[head * 16 + dd] + EPSf);
        float tail = 1.0f / (256.0f + dot);

        float o[16];
        {
            const float4* vs4 = reinterpret_cast<const float4*>(vsum + head * 16);
#pragma unroll
            for (int q4 = 0; q4 < 4; ++q4) {
                float4 v = vs4[q4];
                o[q4*4+0] = v.x; o[q4*4+1] = v.y; o[q4*4+2] = v.z; o[q4*4+3] = v.w;
            }
        }
#pragma unroll
        for (int m2 = 0; m2 < 16; ++m2) {
            float q = qv[m2];
            const float4* kr = reinterpret_cast<const float4*>(kvacc + (head * 16 + m2) * 16);
#pragma unroll
            for (int q4 = 0; q4 < 4; ++q4) {
                float4 v = kr[q4];
                o[q4*4+0] += q * v.x; o[q4*4+1] += q * v.y;
                o[q4*4+2] += q * v.z; o[q4*4+3] += q * v.w;
            }
        }

        const int rr = n >> 4, s2 = n & 15;
        const size_t g0 = base + (size_t)(head * 16) * CH + (size_t)rr * Wdim + s2;
#pragma unroll
        for (int c2 = 0; c2 < 16; ++c2)
            out[g0 + (size_t)c2 * CH] = o[c2] * tail;
    }
}

extern "C" void kernel_launch(void* const* d_in, const int* in_sizes, int n_in,
                              void* d_out, int out_size) {
    const float* x1  = (const float*)d_in[0];
    const float* x2  = (const float*)d_in[1];
    const float* Wq  = (const float*)d_in[2];
    const float* Wkv = (const float*)d_in[3];
    float* out = (float*)d_out;

    cudaFuncSetAttribute(lwm_kernel, cudaFuncAttributeMaxDynamicSharedMemorySize, SMEM_BYTES);
    lwm_kernel<<<NWin, THREADS, SMEM_BYTES>>>(x1, x2, Wq, Wkv, out);
}